// round 1
// baseline (speedup 1.0000x reference)
#include <cuda_runtime.h>
#include <cstdint>

#define NN 16384
#define NF 64
#define NC 16

// Scratch (no allocations allowed): support, h1, h2 — 4 MB each.
__device__ float g_s [NN * NF];
__device__ float g_h1[NN * NF];
__device__ float g_h2[NN * NF];

// ---------------------------------------------------------------------------
// GEMM: C[NN,64] = A[NN,NN] @ B[NN,64]   (fp32 in memory, TF32 tensor cores)
// Block tile 128x64xBK32, 256 threads (8 warps, warp tile 32x32).
// ---------------------------------------------------------------------------
#define BM 128
#define BK 32
#define LDA 36   // smem words per A row (32 k + 4 pad) -> conflict-free frag LDS + aligned STS.128
#define LDB 72   // smem words per B k-row (64 n + 8 pad) -> conflict-free frag LDS

__device__ __forceinline__ uint32_t f2tf(float f) {
    uint32_t u;
    asm("cvt.rna.tf32.f32 %0, %1;" : "=r"(u) : "f"(f));
    return u;
}

__device__ __forceinline__ void mma_tf32(float* c, const uint32_t* a, const uint32_t* b) {
    asm volatile(
        "mma.sync.aligned.m16n8k8.row.col.f32.tf32.tf32.f32 "
        "{%0,%1,%2,%3}, {%4,%5,%6,%7}, {%8,%9}, {%0,%1,%2,%3};"
        : "+f"(c[0]), "+f"(c[1]), "+f"(c[2]), "+f"(c[3])
        : "r"(a[0]), "r"(a[1]), "r"(a[2]), "r"(a[3]),
          "r"(b[0]), "r"(b[1]));
}

__global__ __launch_bounds__(256) void gemm64(const float* __restrict__ A,
                                              const float* __restrict__ B,
                                              float* __restrict__ C) {
    extern __shared__ uint32_t sm[];
    uint32_t* As = sm;                  // [2][BM][LDA]
    uint32_t* Bs = sm + 2 * BM * LDA;   // [2][BK][LDB]

    const int tid  = threadIdx.x;
    const int lane = tid & 31, warp = tid >> 5;
    const int g = lane >> 2, t = lane & 3;       // quad group / thread-in-group
    const int wm = (warp & 3) * 32;              // warp row offset in block tile
    const int wn = (warp >> 2) * 32;             // warp col offset
    const int br = blockIdx.x * BM;

    // global->reg staging indices
    const int arow = tid >> 3;            // 0..31  (A row within 32-row batch)
    const int ak4  = (tid & 7) * 4;       // k offset (float4)
    const int bk   = tid >> 4;            // 0..15  (B k-row within 16-row batch)
    const int bn4  = (tid & 15) * 4;      // n offset (float4)

    float4 ra[4], rb[2];

    auto ldg = [&](int kt) {
        #pragma unroll
        for (int b = 0; b < 4; b++)
            ra[b] = *(const float4*)&A[(size_t)(br + arow + b * 32) * NN + kt + ak4];
        #pragma unroll
        for (int b = 0; b < 2; b++)
            rb[b] = *(const float4*)&B[(size_t)(kt + bk + b * 16) * NF + bn4];
    };
    auto sts = [&](int buf) {
        uint32_t* a_ = As + buf * BM * LDA;
        uint32_t* b_ = Bs + buf * BK * LDB;
        #pragma unroll
        for (int b = 0; b < 4; b++) {
            uint4 v = make_uint4(f2tf(ra[b].x), f2tf(ra[b].y), f2tf(ra[b].z), f2tf(ra[b].w));
            *(uint4*)&a_[(arow + b * 32) * LDA + ak4] = v;
        }
        #pragma unroll
        for (int b = 0; b < 2; b++) {
            uint4 v = make_uint4(f2tf(rb[b].x), f2tf(rb[b].y), f2tf(rb[b].z), f2tf(rb[b].w));
            *(uint4*)&b_[(bk + b * 16) * LDB + bn4] = v;
        }
    };

    float acc[2][4][4];
    #pragma unroll
    for (int im = 0; im < 2; im++)
        #pragma unroll
        for (int in_ = 0; in_ < 4; in_++)
            #pragma unroll
            for (int r = 0; r < 4; r++) acc[im][in_][r] = 0.f;

    const int NT = NN / BK;   // 512 k-tiles

    ldg(0);
    sts(0);
    __syncthreads();
    ldg(BK);

    for (int it = 0; it < NT; ++it) {
        const int cur = it & 1;
        if (it + 1 < NT) sts(cur ^ 1);                 // stage tile it+1
        if (it + 2 < NT) ldg((it + 2) * BK);           // prefetch tile it+2

        const uint32_t* a_ = As + cur * BM * LDA;
        const uint32_t* b_ = Bs + cur * BK * LDB;
        #pragma unroll
        for (int kk = 0; kk < BK; kk += 8) {
            uint32_t af[2][4], bf[4][2];
            #pragma unroll
            for (int im = 0; im < 2; im++) {
                const int r0 = wm + im * 16;
                af[im][0] = a_[(r0 + g    ) * LDA + kk + t    ];
                af[im][1] = a_[(r0 + g + 8) * LDA + kk + t    ];
                af[im][2] = a_[(r0 + g    ) * LDA + kk + t + 4];
                af[im][3] = a_[(r0 + g + 8) * LDA + kk + t + 4];
            }
            #pragma unroll
            for (int in_ = 0; in_ < 4; in_++) {
                bf[in_][0] = b_[(kk + t    ) * LDB + wn + in_ * 8 + g];
                bf[in_][1] = b_[(kk + t + 4) * LDB + wn + in_ * 8 + g];
            }
            #pragma unroll
            for (int im = 0; im < 2; im++)
                #pragma unroll
                for (int in_ = 0; in_ < 4; in_++)
                    mma_tf32(acc[im][in_], af[im], bf[in_]);
        }
        __syncthreads();
    }

    // epilogue: c0:(g,2t) c1:(g,2t+1) c2:(g+8,2t) c3:(g+8,2t+1)
    #pragma unroll
    for (int im = 0; im < 2; im++) {
        #pragma unroll
        for (int in_ = 0; in_ < 4; in_++) {
            const int r0 = br + wm + im * 16 + g;
            const int c0 = wn + in_ * 8 + 2 * t;
            *(float2*)&C[(size_t)r0 * NF + c0]       = make_float2(acc[im][in_][0], acc[im][in_][1]);
            *(float2*)&C[(size_t)(r0 + 8) * NF + c0] = make_float2(acc[im][in_][2], acc[im][in_][3]);
        }
    }
}

// ---------------------------------------------------------------------------
// Fused SAGE layer epilogue: H = relu([X | S] @ W),  W is [128,64] row-major.
// 16 nodes per block, 1024 threads (node, outcol).
// ---------------------------------------------------------------------------
__global__ __launch_bounds__(1024) void layer_kernel(const float* __restrict__ X,
                                                     const float* __restrict__ S,
                                                     const float* __restrict__ W,
                                                     float* __restrict__ H) {
    __shared__ float Ws[128 * 64];
    __shared__ float xs[16 * 64];
    __shared__ float ss[16 * 64];
    const int tid  = threadIdx.x;
    const int base = blockIdx.x * 16 * 64;

    xs[tid] = X[base + tid];
    ss[tid] = S[base + tid];
    #pragma unroll
    for (int i = 0; i < 8; i++) Ws[tid + i * 1024] = W[tid + i * 1024];
    __syncthreads();

    const int j = tid & 63, ni = tid >> 6;
    float acc = 0.f;
    #pragma unroll
    for (int f = 0; f < 64; f++) {
        acc += xs[ni * 64 + f] * Ws[f * 64 + j];
        acc += ss[ni * 64 + f] * Ws[(64 + f) * 64 + j];
    }
    H[base + tid] = fmaxf(acc, 0.f);
}

// ---------------------------------------------------------------------------
// logits = H @ W_lin^T  ->  log_softmax over 16 classes.
// 16 nodes per block, 256 threads = (node, class); 16-lane shfl reductions.
// ---------------------------------------------------------------------------
__global__ __launch_bounds__(256) void logsm_kernel(const float* __restrict__ H,
                                                    const float* __restrict__ WL,
                                                    float* __restrict__ out) {
    __shared__ float Ws[16 * 65];   // stride 65 -> conflict-free across classes
    __shared__ float hs[16 * 64];
    const int tid  = threadIdx.x;
    const int base = blockIdx.x * 16 * 64;

    #pragma unroll
    for (int i = 0; i < 4; i++) {
        const int idx = tid + i * 256;
        Ws[(idx >> 6) * 65 + (idx & 63)] = WL[idx];
        hs[idx] = H[base + idx];
    }
    __syncthreads();

    const int c = tid & 15, ni = tid >> 4;
    float acc = 0.f;
    #pragma unroll
    for (int f = 0; f < 64; f++)
        acc += hs[ni * 64 + f] * Ws[c * 65 + f];

    float m = acc;
    #pragma unroll
    for (int off = 8; off; off >>= 1)
        m = fmaxf(m, __shfl_xor_sync(0xffffffffu, m, off));
    float e = expf(acc - m);
    float s = e;
    #pragma unroll
    for (int off = 8; off; off >>= 1)
        s += __shfl_xor_sync(0xffffffffu, s, off);

    out[blockIdx.x * 16 * 16 + ni * 16 + c] = acc - m - logf(s);
}

// ---------------------------------------------------------------------------
extern "C" void kernel_launch(void* const* d_in, const int* in_sizes, int n_in,
                              void* d_out, int out_size) {
    const float* x   = (const float*)d_in[0];
    const float* adj = (const float*)d_in[1];
    const float* W1  = (const float*)d_in[2];
    const float* W2  = (const float*)d_in[3];
    const float* WL  = (const float*)d_in[4];
    float* out = (float*)d_out;

    void *ps, *ph1, *ph2;
    cudaGetSymbolAddress(&ps,  g_s);
    cudaGetSymbolAddress(&ph1, g_h1);
    cudaGetSymbolAddress(&ph2, g_h2);

    const int smem = (2 * BM * LDA + 2 * BK * LDB) * 4;   // 55296 B
    cudaFuncSetAttribute(gemm64, cudaFuncAttributeMaxDynamicSharedMemorySize, smem);

    // layer 1
    gemm64<<<NN / BM, 256, smem>>>(adj, x, (float*)ps);
    layer_kernel<<<NN / 16, 1024>>>(x, (const float*)ps, W1, (float*)ph1);
    // layer 2
    gemm64<<<NN / BM, 256, smem>>>(adj, (const float*)ph1, (float*)ps);
    layer_kernel<<<NN / 16, 1024>>>((const float*)ph1, (const float*)ps, W2, (float*)ph2);
    // classifier + log_softmax
    logsm_kernel<<<NN / 16, 256>>>((const float*)ph2, WL, out);
}